// round 2
// baseline (speedup 1.0000x reference)
#include <cuda_runtime.h>
#include <cstdint>

// Problem constants
constexpr int Bn   = 8;
constexpr int Cn   = 512;
constexpr int Tn   = 1024;
constexpr int NG   = 32;      // groups
constexpr int CPG  = Cn / NG; // 16 channels per group
constexpr int NH   = 8;       // heads per batch
constexpr int CH   = 64;      // channels per head
constexpr float EPSV = 1e-5f;
constexpr float SCALE2 = 0.125f; // (64^-0.25)^2 = 1/sqrt(64)

// Scratch (device globals: allocation-free rule)
__device__ float g_h  [Bn * Cn   * Tn];   // 16 MB
__device__ float g_qkv[Bn * 1536 * Tn];   // 48 MB
__device__ float g_a  [Bn * Cn   * Tn];   // 16 MB

// ---------------------------------------------------------------------------
// GroupNorm: one block per (b, group). 16 ch x 1024 = 16384 elems.
// ---------------------------------------------------------------------------
__global__ __launch_bounds__(256) void gn_kernel(
    const float* __restrict__ x, const float* __restrict__ gamma,
    const float* __restrict__ beta, float* __restrict__ out)
{
    int bg = blockIdx.x;
    int b = bg >> 5, g = bg & 31;
    const int CNT = CPG * Tn; // 16384
    size_t base = ((size_t)b * Cn + g * CPG) * Tn;

    float s = 0.f, s2 = 0.f;
    for (int i = threadIdx.x; i < CNT; i += 256) {
        float v = x[base + i];
        s += v; s2 += v * v;
    }
    // warp reduce
    #pragma unroll
    for (int o = 16; o > 0; o >>= 1) {
        s  += __shfl_down_sync(0xffffffffu, s,  o);
        s2 += __shfl_down_sync(0xffffffffu, s2, o);
    }
    __shared__ float ws[8], ws2[8], sMean, sRinv;
    int wid = threadIdx.x >> 5, lane = threadIdx.x & 31;
    if (lane == 0) { ws[wid] = s; ws2[wid] = s2; }
    __syncthreads();
    if (threadIdx.x == 0) {
        float ts = 0.f, ts2 = 0.f;
        #pragma unroll
        for (int i = 0; i < 8; i++) { ts += ws[i]; ts2 += ws2[i]; }
        float mean = ts / CNT;
        float var  = ts2 / CNT - mean * mean;
        sMean = mean;
        sRinv = rsqrtf(var + EPSV);
    }
    __syncthreads();
    float mean = sMean, rinv = sRinv;
    for (int i = threadIdx.x; i < CNT; i += 256) {
        int c = g * CPG + (i >> 10);
        out[base + i] = (x[base + i] - mean) * rinv * gamma[c] + beta[c];
    }
}

// ---------------------------------------------------------------------------
// SGEMM: out[b][m][n] = sum_k W[m][k] * X[b][k][n] + bias[m] (+ resid)
// 128x128 tile, 256 threads, 8x8 per thread (split 4+4 halves), K-step 8.
// ---------------------------------------------------------------------------
__global__ __launch_bounds__(256) void sgemm_kernel(
    const float* __restrict__ W, const float* __restrict__ X,
    const float* __restrict__ bias, const float* __restrict__ resid,
    float* __restrict__ out, int O, int C, int T)
{
    int b  = blockIdx.z;
    const float* Xb = X + (size_t)b * C * T;
    float* outb     = out + (size_t)b * O * T;
    const float* rb = resid ? resid + (size_t)b * O * T : nullptr;
    int m0 = blockIdx.y * 128, n0 = blockIdx.x * 128;

    __shared__ float Ws[8][132]; // pad 132: conflict-free, float4-aligned rows
    __shared__ float Xs[8][128];

    int tid = threadIdx.x, tx = tid & 15, ty = tid >> 4;

    float acc[8][8];
    #pragma unroll
    for (int u = 0; u < 8; u++)
        #pragma unroll
        for (int v = 0; v < 8; v++) acc[u][v] = 0.f;

    for (int k0 = 0; k0 < C; k0 += 8) {
        #pragma unroll
        for (int i = 0; i < 4; i++) {
            int e = tid + i * 256;
            int kk = e & 7, m = e >> 3;
            Ws[kk][m] = W[(size_t)(m0 + m) * C + k0 + kk];
        }
        #pragma unroll
        for (int i = 0; i < 4; i++) {
            int e = tid + i * 256;
            int n = e & 127, kk = e >> 7;
            Xs[kk][n] = Xb[(size_t)(k0 + kk) * T + n0 + n];
        }
        __syncthreads();
        #pragma unroll
        for (int kk = 0; kk < 8; kk++) {
            float a[8], bb[8];
            float4 t0 = *(const float4*)&Ws[kk][ty * 4];
            float4 t1 = *(const float4*)&Ws[kk][64 + ty * 4];
            a[0]=t0.x; a[1]=t0.y; a[2]=t0.z; a[3]=t0.w;
            a[4]=t1.x; a[5]=t1.y; a[6]=t1.z; a[7]=t1.w;
            float4 t2 = *(const float4*)&Xs[kk][tx * 4];
            float4 t3 = *(const float4*)&Xs[kk][64 + tx * 4];
            bb[0]=t2.x; bb[1]=t2.y; bb[2]=t2.z; bb[3]=t2.w;
            bb[4]=t3.x; bb[5]=t3.y; bb[6]=t3.z; bb[7]=t3.w;
            #pragma unroll
            for (int u = 0; u < 8; u++)
                #pragma unroll
                for (int v = 0; v < 8; v++)
                    acc[u][v] = fmaf(a[u], bb[v], acc[u][v]);
        }
        __syncthreads();
    }

    #pragma unroll
    for (int u = 0; u < 8; u++) {
        int m = m0 + ((u < 4) ? (ty * 4 + u) : (64 + ty * 4 + u - 4));
        float bi = bias[m];
        #pragma unroll
        for (int v = 0; v < 8; v++) {
            int n = n0 + ((v < 4) ? (tx * 4 + v) : (64 + tx * 4 + v - 4));
            float val = acc[u][v] + bi;
            if (rb) val += rb[(size_t)m * T + n];
            outb[(size_t)m * T + n] = val;
        }
    }
}

// ---------------------------------------------------------------------------
// Flash-style attention. Block = (head hh, 128-query tile qt). 256 threads.
// smem: Qs[64][128], KV (K:[64][128] / V:[128][68]), Ps[128][128].
// ---------------------------------------------------------------------------
constexpr int ATTN_SMEM_FLOATS = 64 * 128 + 128 * 68 + 128 * 128; // 33280
constexpr int ATTN_SMEM_BYTES  = ATTN_SMEM_FLOATS * 4;            // 133120

__global__ __launch_bounds__(256) void attn_kernel(
    const float* __restrict__ qkv, float* __restrict__ a_out)
{
    extern __shared__ float sm[];
    float* Qs = sm;                  // [c][i] stride 128
    float* KV = sm + 64 * 128;       // K: [c][j] stride 128; V: [j][c] stride 68
    float* Ps = sm + 64 * 128 + 128 * 68; // [i][j] stride 128

    int blk = blockIdx.x;
    int qt = blk & 7, hh = blk >> 3;
    int b = hh >> 3, h = hh & 7;
    const float* qb = qkv + ((size_t)b * 1536 + h * 192) * Tn;
    const float* kb = qb + 64 * Tn;
    const float* vb = qb + 128 * Tn;
    int i0 = qt * 128;

    int tid = threadIdx.x, tx = tid & 15, ty = tid >> 4;

    // load Q tile
    for (int e = tid; e < 64 * 128; e += 256) {
        int i = e & 127, c = e >> 7;
        Qs[c * 128 + i] = qb[(size_t)c * Tn + i0 + i];
    }

    float m[8], l[8], acc[8][4];
    #pragma unroll
    for (int u = 0; u < 8; u++) {
        m[u] = -1e30f; l[u] = 0.f;
        #pragma unroll
        for (int v = 0; v < 4; v++) acc[u][v] = 0.f;
    }

    for (int s0 = 0; s0 < Tn; s0 += 128) {
        __syncthreads(); // prior PV done with KV/Ps
        for (int e = tid; e < 64 * 128; e += 256) {
            int j = e & 127, c = e >> 7;
            KV[c * 128 + j] = kb[(size_t)c * Tn + s0 + j];
        }
        __syncthreads();

        // S = (Q^T K) * SCALE2
        float sacc[8][8];
        #pragma unroll
        for (int u = 0; u < 8; u++)
            #pragma unroll
            for (int v = 0; v < 8; v++) sacc[u][v] = 0.f;
        #pragma unroll 8
        for (int c = 0; c < 64; c++) {
            float qa[8], kk[8];
            float4 t0 = *(const float4*)&Qs[c * 128 + ty * 4];
            float4 t1 = *(const float4*)&Qs[c * 128 + 64 + ty * 4];
            qa[0]=t0.x; qa[1]=t0.y; qa[2]=t0.z; qa[3]=t0.w;
            qa[4]=t1.x; qa[5]=t1.y; qa[6]=t1.z; qa[7]=t1.w;
            float4 t2 = *(const float4*)&KV[c * 128 + tx * 4];
            float4 t3 = *(const float4*)&KV[c * 128 + 64 + tx * 4];
            kk[0]=t2.x; kk[1]=t2.y; kk[2]=t2.z; kk[3]=t2.w;
            kk[4]=t3.x; kk[5]=t3.y; kk[6]=t3.z; kk[7]=t3.w;
            #pragma unroll
            for (int u = 0; u < 8; u++)
                #pragma unroll
                for (int v = 0; v < 8; v++)
                    sacc[u][v] = fmaf(qa[u], kk[v], sacc[u][v]);
        }

        // online softmax per row; store P to smem
        #pragma unroll
        for (int u = 0; u < 8; u++) {
            float mx = -1e30f;
            #pragma unroll
            for (int v = 0; v < 8; v++) {
                sacc[u][v] *= SCALE2;
                mx = fmaxf(mx, sacc[u][v]);
            }
            #pragma unroll
            for (int o = 1; o < 16; o <<= 1)
                mx = fmaxf(mx, __shfl_xor_sync(0xffffffffu, mx, o));
            float mn = fmaxf(m[u], mx);
            float rs = 0.f;
            #pragma unroll
            for (int v = 0; v < 8; v++) {
                float p = __expf(sacc[u][v] - mn);
                sacc[u][v] = p; rs += p;
            }
            #pragma unroll
            for (int o = 1; o < 16; o <<= 1)
                rs += __shfl_xor_sync(0xffffffffu, rs, o);
            float corr = __expf(m[u] - mn);
            l[u] = l[u] * corr + rs;
            m[u] = mn;
            #pragma unroll
            for (int v = 0; v < 4; v++) acc[u][v] *= corr;

            int i = (u < 4) ? (ty * 4 + u) : (64 + ty * 4 + u - 4);
            #pragma unroll
            for (int v = 0; v < 4; v++) {
                Ps[i * 128 + tx * 4 + v]      = sacc[u][v];
                Ps[i * 128 + 64 + tx * 4 + v] = sacc[u][4 + v];
            }
        }
        __syncthreads(); // S-compute done reading KV; Ps fully written

        // load V transposed: Vs[j][c], stride 68
        for (int e = tid; e < 64 * 128; e += 256) {
            int j = e & 127, c = e >> 7;
            KV[j * 68 + c] = vb[(size_t)c * Tn + s0 + j];
        }
        __syncthreads();

        // acc[i][c] += sum_j P[i][j] * V[j][c]
        #pragma unroll 4
        for (int j = 0; j < 128; j += 4) {
            float4 vr0 = *(const float4*)&KV[(j + 0) * 68 + tx * 4];
            float4 vr1 = *(const float4*)&KV[(j + 1) * 68 + tx * 4];
            float4 vr2 = *(const float4*)&KV[(j + 2) * 68 + tx * 4];
            float4 vr3 = *(const float4*)&KV[(j + 3) * 68 + tx * 4];
            #pragma unroll
            for (int u = 0; u < 8; u++) {
                int i = (u < 4) ? (ty * 4 + u) : (64 + ty * 4 + u - 4);
                float4 pr = *(const float4*)&Ps[i * 128 + j];
                acc[u][0] = fmaf(pr.x, vr0.x, acc[u][0]);
                acc[u][1] = fmaf(pr.x, vr0.y, acc[u][1]);
                acc[u][2] = fmaf(pr.x, vr0.z, acc[u][2]);
                acc[u][3] = fmaf(pr.x, vr0.w, acc[u][3]);
                acc[u][0] = fmaf(pr.y, vr1.x, acc[u][0]);
                acc[u][1] = fmaf(pr.y, vr1.y, acc[u][1]);
                acc[u][2] = fmaf(pr.y, vr1.z, acc[u][2]);
                acc[u][3] = fmaf(pr.y, vr1.w, acc[u][3]);
                acc[u][0] = fmaf(pr.z, vr2.x, acc[u][0]);
                acc[u][1] = fmaf(pr.z, vr2.y, acc[u][1]);
                acc[u][2] = fmaf(pr.z, vr2.z, acc[u][2]);
                acc[u][3] = fmaf(pr.z, vr2.w, acc[u][3]);
                acc[u][0] = fmaf(pr.w, vr3.x, acc[u][0]);
                acc[u][1] = fmaf(pr.w, vr3.y, acc[u][1]);
                acc[u][2] = fmaf(pr.w, vr3.z, acc[u][2]);
                acc[u][3] = fmaf(pr.w, vr3.w, acc[u][3]);
            }
        }
    }

    // epilogue: a[b][h*64+c][i0+i] = acc / l
    #pragma unroll
    for (int u = 0; u < 8; u++) {
        int i = (u < 4) ? (ty * 4 + u) : (64 + ty * 4 + u - 4);
        float inv = 1.0f / l[u];
        #pragma unroll
        for (int v = 0; v < 4; v++) {
            int c = tx * 4 + v;
            a_out[((size_t)b * Cn + h * CH + c) * Tn + i0 + i] = acc[u][v] * inv;
        }
    }
}

// ---------------------------------------------------------------------------
extern "C" void kernel_launch(void* const* d_in, const int* in_sizes, int n_in,
                              void* d_out, int out_size)
{
    const float* x      = (const float*)d_in[0];
    const float* gamma  = (const float*)d_in[1];
    const float* beta   = (const float*)d_in[2];
    const float* w_qkv  = (const float*)d_in[3];
    const float* b_qkv  = (const float*)d_in[4];
    const float* w_proj = (const float*)d_in[5];
    const float* b_proj = (const float*)d_in[6];
    float* out = (float*)d_out;

    float *h_ptr, *qkv_ptr, *a_ptr;
    cudaGetSymbolAddress((void**)&h_ptr,   g_h);
    cudaGetSymbolAddress((void**)&qkv_ptr, g_qkv);
    cudaGetSymbolAddress((void**)&a_ptr,   g_a);

    cudaFuncSetAttribute(attn_kernel,
                         cudaFuncAttributeMaxDynamicSharedMemorySize,
                         ATTN_SMEM_BYTES);

    // 1. GroupNorm
    gn_kernel<<<Bn * NG, 256>>>(x, gamma, beta, h_ptr);

    // 2. QKV GEMM: O=1536
    sgemm_kernel<<<dim3(Tn / 128, 1536 / 128, Bn), 256>>>(
        w_qkv, h_ptr, b_qkv, nullptr, qkv_ptr, 1536, Cn, Tn);

    // 3. Attention: 64 heads x 8 query tiles
    attn_kernel<<<Bn * NH * (Tn / 128), 256, ATTN_SMEM_BYTES>>>(qkv_ptr, a_ptr);

    // 4. Proj GEMM + bias + residual
    sgemm_kernel<<<dim3(Tn / 128, Cn / 128, Bn), 256>>>(
        w_proj, a_ptr, b_proj, x, out, Cn, Cn, Tn);
}

// round 4
// speedup vs baseline: 2.4243x; 2.4243x over previous
#include <cuda_runtime.h>
#include <cstdint>

// Problem constants
constexpr int Bn   = 8;
constexpr int Cn   = 512;
constexpr int Tn   = 1024;
constexpr int NG   = 32;
constexpr int CPG  = Cn / NG;
constexpr int NH   = 8;
constexpr int CH   = 64;
constexpr float EPSV = 1e-5f;

// Scratch (device globals: allocation-free rule)
__device__ float g_h  [Bn * Cn   * Tn];
__device__ float g_qkv[Bn * 1536 * Tn];
__device__ float g_a  [Bn * Cn   * Tn];

// ---------------------------------------------------------------------------
// tf32 helpers
// ---------------------------------------------------------------------------
__device__ __forceinline__ float tf32r(float x) {
    uint32_t u;
    asm("cvt.rna.tf32.f32 %0, %1;" : "=r"(u) : "f"(x));
    return __uint_as_float(u);
}
__device__ __forceinline__ uint32_t f2u(float x) { return __float_as_uint(x); }

// D += A(16x8 row) * B(8x8 col);  fp32 accum, tf32 inputs
__device__ __forceinline__ void mma_tf32(float* c,
    uint32_t a0, uint32_t a1, uint32_t a2, uint32_t a3,
    uint32_t b0, uint32_t b1)
{
    asm volatile(
        "mma.sync.aligned.m16n8k8.row.col.f32.tf32.tf32.f32 "
        "{%0,%1,%2,%3}, {%4,%5,%6,%7}, {%8,%9}, {%0,%1,%2,%3};\n"
        : "+f"(c[0]), "+f"(c[1]), "+f"(c[2]), "+f"(c[3])
        : "r"(a0), "r"(a1), "r"(a2), "r"(a3), "r"(b0), "r"(b1));
}

// ---------------------------------------------------------------------------
// GroupNorm (HBM-bound, ~15us)
// ---------------------------------------------------------------------------
__global__ __launch_bounds__(256) void gn_kernel(
    const float* __restrict__ x, const float* __restrict__ gamma,
    const float* __restrict__ beta, float* __restrict__ out)
{
    int bg = blockIdx.x;
    int b = bg >> 5, g = bg & 31;
    const int CNT = CPG * Tn;
    size_t base = ((size_t)b * Cn + g * CPG) * Tn;

    float s = 0.f, s2 = 0.f;
    for (int i = threadIdx.x; i < CNT; i += 256) {
        float v = x[base + i];
        s += v; s2 += v * v;
    }
    #pragma unroll
    for (int o = 16; o > 0; o >>= 1) {
        s  += __shfl_down_sync(0xffffffffu, s,  o);
        s2 += __shfl_down_sync(0xffffffffu, s2, o);
    }
    __shared__ float ws[8], ws2[8], sMean, sRinv;
    int wid = threadIdx.x >> 5, lane = threadIdx.x & 31;
    if (lane == 0) { ws[wid] = s; ws2[wid] = s2; }
    __syncthreads();
    if (threadIdx.x == 0) {
        float ts = 0.f, ts2 = 0.f;
        #pragma unroll
        for (int i = 0; i < 8; i++) { ts += ws[i]; ts2 += ws2[i]; }
        float mean = ts / CNT;
        float var  = ts2 / CNT - mean * mean;
        sMean = mean;
        sRinv = rsqrtf(var + EPSV);
    }
    __syncthreads();
    float mean = sMean, rinv = sRinv;
    for (int i = threadIdx.x; i < CNT; i += 256) {
        int c = g * CPG + (i >> 10);
        out[base + i] = (x[base + i] - mean) * rinv * gamma[c] + beta[c];
    }
}

// ---------------------------------------------------------------------------
// tf32 tensor-core SGEMM: out[b][m][n] = sum_k W[m][k] X[b][k][n] + bias (+res)
// 128x128 block tile, 8 warps (4m x 2n), warp tile 32x64, k-step 16.
// SMEM strides: Ws 20 (20%32=20 -> a-frag conflict-free),
//               Xs 136 (>=128 cols!, 136%32=8 -> b-frag conflict-free).
// ---------------------------------------------------------------------------
constexpr int WS_S = 20;
constexpr int XS_S = 136;   // was 40 in round 3: overflowed the 128-wide tile

__global__ __launch_bounds__(256) void sgemm_tf32(
    const float* __restrict__ W, const float* __restrict__ X,
    const float* __restrict__ bias, const float* __restrict__ resid,
    float* __restrict__ out, int O, int C, int T)
{
    __shared__ float Ws[128 * WS_S];   // 10,240 B
    __shared__ float Xs[16 * XS_S];    //  8,704 B

    int b  = blockIdx.z;
    const float* Xb = X + (size_t)b * C * T;
    float* outb     = out + (size_t)b * O * T;
    const float* rb = resid ? resid + (size_t)b * O * T : nullptr;
    int m0 = blockIdx.y * 128, n0 = blockIdx.x * 128;

    int tid = threadIdx.x, warp = tid >> 5, lane = tid & 31;
    int gid = lane >> 2, tig = lane & 3;
    int wm = warp >> 1;          // 0..3 -> m offset wm*32
    int wn = warp & 1;           // 0..1 -> n offset wn*64

    float acc[2][8][4];
    #pragma unroll
    for (int mt = 0; mt < 2; mt++)
        #pragma unroll
        for (int nt = 0; nt < 8; nt++)
            #pragma unroll
            for (int q = 0; q < 4; q++) acc[mt][nt][q] = 0.f;

    for (int k0 = 0; k0 < C; k0 += 16) {
        // load W tile 128x16 (row m, col k), tf32-rounded. 512 float4s.
        #pragma unroll
        for (int it = 0; it < 2; it++) {
            int e = tid + it * 256;
            int m = e >> 2, kq = e & 3;
            float4 v = *(const float4*)&W[(size_t)(m0 + m) * C + k0 + kq * 4];
            float4 r = make_float4(tf32r(v.x), tf32r(v.y), tf32r(v.z), tf32r(v.w));
            *(float4*)&Ws[m * WS_S + kq * 4] = r;
        }
        // load X tile 16x128 (row k, col n). 512 float4s.
        #pragma unroll
        for (int it = 0; it < 2; it++) {
            int e = tid + it * 256;
            int k = e >> 5, nq = e & 31;
            float4 v = *(const float4*)&Xb[(size_t)(k0 + k) * T + n0 + nq * 4];
            float4 r = make_float4(tf32r(v.x), tf32r(v.y), tf32r(v.z), tf32r(v.w));
            *(float4*)&Xs[k * XS_S + nq * 4] = r;
        }
        __syncthreads();

        #pragma unroll
        for (int kh = 0; kh < 16; kh += 8) {
            uint32_t a[2][4];
            #pragma unroll
            for (int mt = 0; mt < 2; mt++) {
                int rbse = wm * 32 + mt * 16;
                a[mt][0] = f2u(Ws[(rbse + gid    ) * WS_S + kh + tig    ]);
                a[mt][1] = f2u(Ws[(rbse + gid + 8) * WS_S + kh + tig    ]);
                a[mt][2] = f2u(Ws[(rbse + gid    ) * WS_S + kh + tig + 4]);
                a[mt][3] = f2u(Ws[(rbse + gid + 8) * WS_S + kh + tig + 4]);
            }
            #pragma unroll
            for (int nt = 0; nt < 8; nt++) {
                int cb = wn * 64 + nt * 8;
                uint32_t b0 = f2u(Xs[(kh + tig    ) * XS_S + cb + gid]);
                uint32_t b1 = f2u(Xs[(kh + tig + 4) * XS_S + cb + gid]);
                #pragma unroll
                for (int mt = 0; mt < 2; mt++)
                    mma_tf32(acc[mt][nt], a[mt][0], a[mt][1], a[mt][2], a[mt][3], b0, b1);
            }
        }
        __syncthreads();
    }

    // epilogue
    #pragma unroll
    for (int mt = 0; mt < 2; mt++) {
        #pragma unroll
        for (int rr = 0; rr < 2; rr++) {
            int m = m0 + wm * 32 + mt * 16 + gid + rr * 8;
            float bi = bias[m];
            #pragma unroll
            for (int nt = 0; nt < 8; nt++) {
                int n = n0 + wn * 64 + nt * 8 + 2 * tig;
                float v0 = acc[mt][nt][rr * 2 + 0] + bi;
                float v1 = acc[mt][nt][rr * 2 + 1] + bi;
                if (rb) {
                    v0 += rb[(size_t)m * T + n];
                    v1 += rb[(size_t)m * T + n + 1];
                }
                *(float2*)&outb[(size_t)m * T + n] = make_float2(v0, v1);
            }
        }
    }
}

// ---------------------------------------------------------------------------
// Flash attention with tf32 mma. Block = (head, 128-query tile). 8 warps.
// Warp owns 16 full S rows -> softmax needs only quad shuffles.
// SMEM: Qs[128][68] (i-major), Ks[64][136], Vs[64][132] (c-major),
//       Ps[128][132] (i-major). All fragment loads conflict-free by stride.
// ---------------------------------------------------------------------------
constexpr int QS_S = 68;   // %32 == 4  : a-frag (i=gid, c=tig) distinct banks
constexpr int KS_S = 136;  // %32 == 8  : b-frag (c=tig, j=gid) distinct banks
constexpr int VS_S = 132;  // %32 == 4  : b-frag (c=gid, j=tig) distinct banks
constexpr int PS_S = 132;  // %32 == 4  : a-frag (i=gid, j=tig) distinct banks

constexpr int ATTN_SMEM_FLOATS = 128 * QS_S + 64 * KS_S + 64 * VS_S + 128 * PS_S;
constexpr int ATTN_SMEM_BYTES  = ATTN_SMEM_FLOATS * 4;  // 171,008 B

__global__ __launch_bounds__(256) void attn_kernel(
    const float* __restrict__ qkv, float* __restrict__ a_out)
{
    extern __shared__ float sm[];
    float* Qs = sm;                      // [i][c]
    float* Ks = Qs + 128 * QS_S;         // [c][j]
    float* Vs = Ks + 64 * KS_S;          // [c][j]
    float* Ps = Vs + 64 * VS_S;          // [i][j]

    int blk = blockIdx.x;
    int qt = blk & 7, hh = blk >> 3;
    int b = hh >> 3, h = hh & 7;
    const float* qb = qkv + ((size_t)b * 1536 + h * 192) * Tn;
    const float* kb = qb + 64 * Tn;
    const float* vb = qb + 128 * Tn;
    int i0 = qt * 128;

    int tid = threadIdx.x, warp = tid >> 5, lane = tid & 31;
    int gid = lane >> 2, tig = lane & 3;
    int rA = warp * 16 + gid;        // first row this thread accumulates
    // (second row is rA + 8)

    // load Q transposed into Qs[i][c], pre-scaled by 1/8 (= ch^-0.5), tf32
    for (int e = tid; e < 64 * 128; e += 256) {
        int c = e >> 7, i = e & 127;
        Qs[i * QS_S + c] = tf32r(qb[(size_t)c * Tn + i0 + i] * 0.125f);
    }

    float mrow0 = -1e30f, mrow1 = -1e30f;
    float lrow0 = 0.f, lrow1 = 0.f;
    float oacc[8][4];
    #pragma unroll
    for (int nt = 0; nt < 8; nt++)
        #pragma unroll
        for (int q = 0; q < 4; q++) oacc[nt][q] = 0.f;

    for (int s0 = 0; s0 < Tn; s0 += 128) {
        __syncthreads();   // prior PV done with Vs; Qs ready on first pass
        // stage K and V tiles (coalesced, conflict-free stores)
        for (int e = tid; e < 64 * 128; e += 256) {
            int c = e >> 7, j = e & 127;
            Ks[c * KS_S + j] = tf32r(kb[(size_t)c * Tn + s0 + j]);
            Vs[c * VS_S + j] = tf32r(vb[(size_t)c * Tn + s0 + j]);
        }
        __syncthreads();

        // ---- S = Q^T K : rows [warp*16, +16), cols 0..127 ----
        float sacc[16][4];
        #pragma unroll
        for (int nt = 0; nt < 16; nt++)
            #pragma unroll
            for (int q = 0; q < 4; q++) sacc[nt][q] = 0.f;

        #pragma unroll
        for (int c0 = 0; c0 < 64; c0 += 8) {
            uint32_t a0 = f2u(Qs[(rA    ) * QS_S + c0 + tig    ]);
            uint32_t a1 = f2u(Qs[(rA + 8) * QS_S + c0 + tig    ]);
            uint32_t a2 = f2u(Qs[(rA    ) * QS_S + c0 + tig + 4]);
            uint32_t a3 = f2u(Qs[(rA + 8) * QS_S + c0 + tig + 4]);
            #pragma unroll
            for (int nt = 0; nt < 16; nt++) {
                uint32_t b0 = f2u(Ks[(c0 + tig    ) * KS_S + nt * 8 + gid]);
                uint32_t b1 = f2u(Ks[(c0 + tig + 4) * KS_S + nt * 8 + gid]);
                mma_tf32(sacc[nt], a0, a1, a2, a3, b0, b1);
            }
        }

        // ---- online softmax (rows rA and rA+8; reduce across quad) ----
        float mx0 = -1e30f, mx1 = -1e30f;
        #pragma unroll
        for (int nt = 0; nt < 16; nt++) {
            mx0 = fmaxf(mx0, fmaxf(sacc[nt][0], sacc[nt][1]));
            mx1 = fmaxf(mx1, fmaxf(sacc[nt][2], sacc[nt][3]));
        }
        mx0 = fmaxf(mx0, __shfl_xor_sync(0xffffffffu, mx0, 1));
        mx0 = fmaxf(mx0, __shfl_xor_sync(0xffffffffu, mx0, 2));
        mx1 = fmaxf(mx1, __shfl_xor_sync(0xffffffffu, mx1, 1));
        mx1 = fmaxf(mx1, __shfl_xor_sync(0xffffffffu, mx1, 2));
        float mn0 = fmaxf(mrow0, mx0), mn1 = fmaxf(mrow1, mx1);
        float corr0 = __expf(mrow0 - mn0), corr1 = __expf(mrow1 - mn1);
        mrow0 = mn0; mrow1 = mn1;

        float rs0 = 0.f, rs1 = 0.f;
        #pragma unroll
        for (int nt = 0; nt < 16; nt++) {
            float p0 = __expf(sacc[nt][0] - mn0);
            float p1 = __expf(sacc[nt][1] - mn0);
            float p2 = __expf(sacc[nt][2] - mn1);
            float p3 = __expf(sacc[nt][3] - mn1);
            rs0 += p0 + p1;  rs1 += p2 + p3;
            int cb = nt * 8 + 2 * tig;
            *(float2*)&Ps[(rA    ) * PS_S + cb] = make_float2(tf32r(p0), tf32r(p1));
            *(float2*)&Ps[(rA + 8) * PS_S + cb] = make_float2(tf32r(p2), tf32r(p3));
        }
        rs0 += __shfl_xor_sync(0xffffffffu, rs0, 1);
        rs0 += __shfl_xor_sync(0xffffffffu, rs0, 2);
        rs1 += __shfl_xor_sync(0xffffffffu, rs1, 1);
        rs1 += __shfl_xor_sync(0xffffffffu, rs1, 2);
        lrow0 = lrow0 * corr0 + rs0;
        lrow1 = lrow1 * corr1 + rs1;
        #pragma unroll
        for (int nt = 0; nt < 8; nt++) {
            oacc[nt][0] *= corr0; oacc[nt][1] *= corr0;
            oacc[nt][2] *= corr1; oacc[nt][3] *= corr1;
        }
        __syncwarp();   // warp reads only its own Ps rows -> warp sync suffices

        // ---- O += P * V : rows same 16, cols 0..63 ----
        #pragma unroll
        for (int j0 = 0; j0 < 128; j0 += 8) {
            uint32_t a0 = f2u(Ps[(rA    ) * PS_S + j0 + tig    ]);
            uint32_t a1 = f2u(Ps[(rA + 8) * PS_S + j0 + tig    ]);
            uint32_t a2 = f2u(Ps[(rA    ) * PS_S + j0 + tig + 4]);
            uint32_t a3 = f2u(Ps[(rA + 8) * PS_S + j0 + tig + 4]);
            #pragma unroll
            for (int nt = 0; nt < 8; nt++) {
                uint32_t b0 = f2u(Vs[(nt * 8 + gid) * VS_S + j0 + tig    ]);
                uint32_t b1 = f2u(Vs[(nt * 8 + gid) * VS_S + j0 + tig + 4]);
                mma_tf32(oacc[nt], a0, a1, a2, a3, b0, b1);
            }
        }
    }

    // epilogue: a[b][h*64+c][i0+i] = oacc / l
    float inv0 = 1.f / lrow0, inv1 = 1.f / lrow1;
    size_t obase = ((size_t)b * Cn + h * CH) * Tn + i0;
    #pragma unroll
    for (int nt = 0; nt < 8; nt++) {
        int c = nt * 8 + 2 * tig;
        a_out[obase + (size_t)(c    ) * Tn + rA    ] = oacc[nt][0] * inv0;
        a_out[obase + (size_t)(c + 1) * Tn + rA    ] = oacc[nt][1] * inv0;
        a_out[obase + (size_t)(c    ) * Tn + rA + 8] = oacc[nt][2] * inv1;
        a_out[obase + (size_t)(c + 1) * Tn + rA + 8] = oacc[nt][3] * inv1;
    }
}

// ---------------------------------------------------------------------------
extern "C" void kernel_launch(void* const* d_in, const int* in_sizes, int n_in,
                              void* d_out, int out_size)
{
    const float* x      = (const float*)d_in[0];
    const float* gamma  = (const float*)d_in[1];
    const float* beta   = (const float*)d_in[2];
    const float* w_qkv  = (const float*)d_in[3];
    const float* b_qkv  = (const float*)d_in[4];
    const float* w_proj = (const float*)d_in[5];
    const float* b_proj = (const float*)d_in[6];
    float* out = (float*)d_out;

    float *h_ptr, *qkv_ptr, *a_ptr;
    cudaGetSymbolAddress((void**)&h_ptr,   g_h);
    cudaGetSymbolAddress((void**)&qkv_ptr, g_qkv);
    cudaGetSymbolAddress((void**)&a_ptr,   g_a);

    cudaFuncSetAttribute(attn_kernel,
                         cudaFuncAttributeMaxDynamicSharedMemorySize,
                         ATTN_SMEM_BYTES);

    // 1. GroupNorm
    gn_kernel<<<Bn * NG, 256>>>(x, gamma, beta, h_ptr);

    // 2. QKV GEMM (tf32 tensor cores)
    sgemm_tf32<<<dim3(Tn / 128, 1536 / 128, Bn), 256>>>(
        w_qkv, h_ptr, b_qkv, nullptr, qkv_ptr, 1536, Cn, Tn);

    // 3. Attention (tf32 tensor cores)
    attn_kernel<<<Bn * NH * (Tn / 128), 256, ATTN_SMEM_BYTES>>>(qkv_ptr, a_ptr);

    // 4. Proj GEMM + bias + residual (tf32 tensor cores)
    sgemm_tf32<<<dim3(Tn / 128, Cn / 128, Bn), 256>>>(
        w_proj, a_ptr, b_proj, x, out, Cn, Cn, Tn);
}

// round 5
// speedup vs baseline: 3.0906x; 1.2749x over previous
#include <cuda_runtime.h>
#include <cstdint>

// Problem constants
constexpr int Bn   = 8;
constexpr int Cn   = 512;
constexpr int Tn   = 1024;
constexpr int NG   = 32;
constexpr int CPG  = Cn / NG;
constexpr int NH   = 8;
constexpr int CH   = 64;
constexpr float EPSV = 1e-5f;

// Scratch (device globals: allocation-free rule)
__device__ float g_h  [Bn * Cn   * Tn];
__device__ float g_qkv[Bn * 1536 * Tn];
__device__ float g_a  [Bn * Cn   * Tn];

// ---------------------------------------------------------------------------
// tf32 helpers
// ---------------------------------------------------------------------------
__device__ __forceinline__ float tf32r(float x) {
    uint32_t u;
    asm("cvt.rna.tf32.f32 %0, %1;" : "=r"(u) : "f"(x));
    return __uint_as_float(u);
}
__device__ __forceinline__ float4 tf32r4(float4 v) {
    return make_float4(tf32r(v.x), tf32r(v.y), tf32r(v.z), tf32r(v.w));
}
__device__ __forceinline__ uint32_t f2u(float x) { return __float_as_uint(x); }

// D += A(16x8 row) * B(8x8 col);  fp32 accum, tf32 inputs
__device__ __forceinline__ void mma_tf32(float* c,
    uint32_t a0, uint32_t a1, uint32_t a2, uint32_t a3,
    uint32_t b0, uint32_t b1)
{
    asm volatile(
        "mma.sync.aligned.m16n8k8.row.col.f32.tf32.tf32.f32 "
        "{%0,%1,%2,%3}, {%4,%5,%6,%7}, {%8,%9}, {%0,%1,%2,%3};\n"
        : "+f"(c[0]), "+f"(c[1]), "+f"(c[2]), "+f"(c[3])
        : "r"(a0), "r"(a1), "r"(a2), "r"(a3), "r"(b0), "r"(b1));
}

// ---------------------------------------------------------------------------
// GroupNorm (HBM-bound, ~15us)
// ---------------------------------------------------------------------------
__global__ __launch_bounds__(256) void gn_kernel(
    const float* __restrict__ x, const float* __restrict__ gamma,
    const float* __restrict__ beta, float* __restrict__ out)
{
    int bg = blockIdx.x;
    int b = bg >> 5, g = bg & 31;
    const int CNT = CPG * Tn;
    size_t base = ((size_t)b * Cn + g * CPG) * Tn;

    float s = 0.f, s2 = 0.f;
    for (int i = threadIdx.x; i < CNT; i += 256) {
        float v = x[base + i];
        s += v; s2 += v * v;
    }
    #pragma unroll
    for (int o = 16; o > 0; o >>= 1) {
        s  += __shfl_down_sync(0xffffffffu, s,  o);
        s2 += __shfl_down_sync(0xffffffffu, s2, o);
    }
    __shared__ float ws[8], ws2[8], sMean, sRinv;
    int wid = threadIdx.x >> 5, lane = threadIdx.x & 31;
    if (lane == 0) { ws[wid] = s; ws2[wid] = s2; }
    __syncthreads();
    if (threadIdx.x == 0) {
        float ts = 0.f, ts2 = 0.f;
        #pragma unroll
        for (int i = 0; i < 8; i++) { ts += ws[i]; ts2 += ws2[i]; }
        float mean = ts / CNT;
        float var  = ts2 / CNT - mean * mean;
        sMean = mean;
        sRinv = rsqrtf(var + EPSV);
    }
    __syncthreads();
    float mean = sMean, rinv = sRinv;
    for (int i = threadIdx.x; i < CNT; i += 256) {
        int c = g * CPG + (i >> 10);
        out[base + i] = (x[base + i] - mean) * rinv * gamma[c] + beta[c];
    }
}

// ---------------------------------------------------------------------------
// tf32 tensor-core SGEMM, software-pipelined with double-buffered SMEM.
// out[b][m][n] = sum_k W[m][k] X[b][k][n] + bias (+res)
// 128x128 block tile, 8 warps (4m x 2n), warp tile 32x64, k-step 16.
// One __syncthreads per k-tile; next tile's gmem loads overlap compute.
// ---------------------------------------------------------------------------
constexpr int WS_S = 20;    // 20%32=20 -> a-frag conflict-free
constexpr int XS_S = 136;   // >=128 cols, 136%32=8 -> b-frag conflict-free

__global__ __launch_bounds__(256, 2) void sgemm_tf32(
    const float* __restrict__ W, const float* __restrict__ X,
    const float* __restrict__ bias, const float* __restrict__ resid,
    float* __restrict__ out, int O, int C, int T)
{
    __shared__ float Ws[2][128 * WS_S];
    __shared__ float Xs[2][16 * XS_S];

    int b  = blockIdx.z;
    const float* Xb = X + (size_t)b * C * T;
    float* outb     = out + (size_t)b * O * T;
    const float* rb = resid ? resid + (size_t)b * O * T : nullptr;
    int m0 = blockIdx.y * 128, n0 = blockIdx.x * 128;

    int tid = threadIdx.x, warp = tid >> 5, lane = tid & 31;
    int gid = lane >> 2, tig = lane & 3;
    int wm = warp >> 1;
    int wn = warp & 1;

    // staging indices (fixed per thread)
    int wm_r0 = tid >> 2,            wk_r0 = (tid & 3) * 4;        // W elems 0..255
    int wm_r1 = (tid + 256) >> 2,    wk_r1 = wk_r0;                // W elems 256..511
    int xk_r0 = tid >> 5,            xn_r0 = (tid & 31) * 4;       // X elems 0..255
    int xk_r1 = (tid + 256) >> 5,    xn_r1 = xn_r0;                // X elems 256..511

    float acc[2][8][4];
    #pragma unroll
    for (int mt = 0; mt < 2; mt++)
        #pragma unroll
        for (int nt = 0; nt < 8; nt++)
            #pragma unroll
            for (int q = 0; q < 4; q++) acc[mt][nt][q] = 0.f;

    // prologue: prefetch tile 0
    float4 wr0 = *(const float4*)&W[(size_t)(m0 + wm_r0) * C + wk_r0];
    float4 wr1 = *(const float4*)&W[(size_t)(m0 + wm_r1) * C + wk_r1];
    float4 xr0 = *(const float4*)&Xb[(size_t)xk_r0 * T + n0 + xn_r0];
    float4 xr1 = *(const float4*)&Xb[(size_t)xk_r1 * T + n0 + xn_r1];

    int nk = C >> 4;
    for (int i = 0; i < nk; i++) {
        int p = i & 1;
        // commit prefetched tile to smem (tf32-rounded)
        *(float4*)&Ws[p][wm_r0 * WS_S + wk_r0] = tf32r4(wr0);
        *(float4*)&Ws[p][wm_r1 * WS_S + wk_r1] = tf32r4(wr1);
        *(float4*)&Xs[p][xk_r0 * XS_S + xn_r0] = tf32r4(xr0);
        *(float4*)&Xs[p][xk_r1 * XS_S + xn_r1] = tf32r4(xr1);
        __syncthreads();

        // issue next tile's gmem loads (land during compute)
        if (i + 1 < nk) {
            int k0 = (i + 1) << 4;
            wr0 = *(const float4*)&W[(size_t)(m0 + wm_r0) * C + k0 + wk_r0];
            wr1 = *(const float4*)&W[(size_t)(m0 + wm_r1) * C + k0 + wk_r1];
            xr0 = *(const float4*)&Xb[(size_t)(k0 + xk_r0) * T + n0 + xn_r0];
            xr1 = *(const float4*)&Xb[(size_t)(k0 + xk_r1) * T + n0 + xn_r1];
        }

        #pragma unroll
        for (int kh = 0; kh < 16; kh += 8) {
            uint32_t a[2][4];
            #pragma unroll
            for (int mt = 0; mt < 2; mt++) {
                int rbse = wm * 32 + mt * 16;
                a[mt][0] = f2u(Ws[p][(rbse + gid    ) * WS_S + kh + tig    ]);
                a[mt][1] = f2u(Ws[p][(rbse + gid + 8) * WS_S + kh + tig    ]);
                a[mt][2] = f2u(Ws[p][(rbse + gid    ) * WS_S + kh + tig + 4]);
                a[mt][3] = f2u(Ws[p][(rbse + gid + 8) * WS_S + kh + tig + 4]);
            }
            #pragma unroll
            for (int nt = 0; nt < 8; nt++) {
                int cb = wn * 64 + nt * 8;
                uint32_t b0 = f2u(Xs[p][(kh + tig    ) * XS_S + cb + gid]);
                uint32_t b1 = f2u(Xs[p][(kh + tig + 4) * XS_S + cb + gid]);
                #pragma unroll
                for (int mt = 0; mt < 2; mt++)
                    mma_tf32(acc[mt][nt], a[mt][0], a[mt][1], a[mt][2], a[mt][3], b0, b1);
            }
        }
    }

    // epilogue
    #pragma unroll
    for (int mt = 0; mt < 2; mt++) {
        #pragma unroll
        for (int rr = 0; rr < 2; rr++) {
            int m = m0 + wm * 32 + mt * 16 + gid + rr * 8;
            float bi = bias[m];
            #pragma unroll
            for (int nt = 0; nt < 8; nt++) {
                int n = n0 + wn * 64 + nt * 8 + 2 * tig;
                float v0 = acc[mt][nt][rr * 2 + 0] + bi;
                float v1 = acc[mt][nt][rr * 2 + 1] + bi;
                if (rb) {
                    v0 += rb[(size_t)m * T + n];
                    v1 += rb[(size_t)m * T + n + 1];
                }
                *(float2*)&outb[(size_t)m * T + n] = make_float2(v0, v1);
            }
        }
    }
}

// ---------------------------------------------------------------------------
// Flash attention, tf32 mma, 64-wide S tiles (16 iters) so SMEM = 105 KB ->
// 2 CTAs/SM (16 warps) for latency hiding. Warp owns 16 full S rows.
// SMEM: Qs[128][68] (i-major), Ks[64][72], Vs[64][68] (c-major),
//       Ps[128][72] (i-major). All fragment loads conflict-free by stride.
// ---------------------------------------------------------------------------
constexpr int QS_S = 68;   // %32==4 : a-frag (gid*4+tig) distinct banks
constexpr int KS_S = 72;   // %32==8 : b-frag (tig*8+gid) distinct banks
constexpr int VS_S = 68;   // %32==4 : b-frag (gid*4+tig) distinct banks
constexpr int PS_S = 72;   // %32==8 : a-frag (gid*8+tig) distinct banks

constexpr int ATTN_SMEM_FLOATS = 128 * QS_S + 64 * KS_S + 64 * VS_S + 128 * PS_S;
constexpr int ATTN_SMEM_BYTES  = ATTN_SMEM_FLOATS * 4;  // 107,520 B

__global__ __launch_bounds__(256, 2) void attn_kernel(
    const float* __restrict__ qkv, float* __restrict__ a_out)
{
    extern __shared__ float sm[];
    float* Qs = sm;                      // [i][c]
    float* Ks = Qs + 128 * QS_S;         // [c][j]
    float* Vs = Ks + 64 * KS_S;          // [c][j]
    float* Ps = Vs + 64 * VS_S;          // [i][j]

    int blk = blockIdx.x;
    int qt = blk & 7, hh = blk >> 3;
    int b = hh >> 3, h = hh & 7;
    const float* qb = qkv + ((size_t)b * 1536 + h * 192) * Tn;
    const float* kb = qb + 64 * Tn;
    const float* vb = qb + 128 * Tn;
    int i0 = qt * 128;

    int tid = threadIdx.x, warp = tid >> 5, lane = tid & 31;
    int gid = lane >> 2, tig = lane & 3;
    int rA = warp * 16 + gid;        // first row; second is rA + 8

    // load Q transposed into Qs[i][c], pre-scaled by 1/8 (= ch^-0.5), tf32
    for (int e = tid; e < 64 * 128; e += 256) {
        int c = e >> 7, i = e & 127;
        Qs[i * QS_S + c] = tf32r(qb[(size_t)c * Tn + i0 + i] * 0.125f);
    }

    float mrow0 = -1e30f, mrow1 = -1e30f;
    float lrow0 = 0.f, lrow1 = 0.f;
    float oacc[8][4];
    #pragma unroll
    for (int nt = 0; nt < 8; nt++)
        #pragma unroll
        for (int q = 0; q < 4; q++) oacc[nt][q] = 0.f;

    for (int s0 = 0; s0 < Tn; s0 += 64) {
        __syncthreads();   // prior PV done with Vs; Qs ready on first pass
        // stage K and V 64x64 tiles (coalesced; interleaved for MLP)
        #pragma unroll
        for (int e = tid; e < 64 * 64; e += 256) {
            int c = e >> 6, j = e & 63;
            Ks[c * KS_S + j] = tf32r(kb[(size_t)c * Tn + s0 + j]);
            Vs[c * VS_S + j] = tf32r(vb[(size_t)c * Tn + s0 + j]);
        }
        __syncthreads();

        // ---- S = Q^T K : rows [warp*16,+16), cols 0..63 ----
        float sacc[8][4];
        #pragma unroll
        for (int nt = 0; nt < 8; nt++)
            #pragma unroll
            for (int q = 0; q < 4; q++) sacc[nt][q] = 0.f;

        #pragma unroll
        for (int c0 = 0; c0 < 64; c0 += 8) {
            uint32_t a0 = f2u(Qs[(rA    ) * QS_S + c0 + tig    ]);
            uint32_t a1 = f2u(Qs[(rA + 8) * QS_S + c0 + tig    ]);
            uint32_t a2 = f2u(Qs[(rA    ) * QS_S + c0 + tig + 4]);
            uint32_t a3 = f2u(Qs[(rA + 8) * QS_S + c0 + tig + 4]);
            #pragma unroll
            for (int nt = 0; nt < 8; nt++) {
                uint32_t b0 = f2u(Ks[(c0 + tig    ) * KS_S + nt * 8 + gid]);
                uint32_t b1 = f2u(Ks[(c0 + tig + 4) * KS_S + nt * 8 + gid]);
                mma_tf32(sacc[nt], a0, a1, a2, a3, b0, b1);
            }
        }

        // ---- online softmax (rows rA and rA+8; reduce across quad) ----
        float mx0 = -1e30f, mx1 = -1e30f;
        #pragma unroll
        for (int nt = 0; nt < 8; nt++) {
            mx0 = fmaxf(mx0, fmaxf(sacc[nt][0], sacc[nt][1]));
            mx1 = fmaxf(mx1, fmaxf(sacc[nt][2], sacc[nt][3]));
        }
        mx0 = fmaxf(mx0, __shfl_xor_sync(0xffffffffu, mx0, 1));
        mx0 = fmaxf(mx0, __shfl_xor_sync(0xffffffffu, mx0, 2));
        mx1 = fmaxf(mx1, __shfl_xor_sync(0xffffffffu, mx1, 1));
        mx1 = fmaxf(mx1, __shfl_xor_sync(0xffffffffu, mx1, 2));
        float mn0 = fmaxf(mrow0, mx0), mn1 = fmaxf(mrow1, mx1);
        float corr0 = __expf(mrow0 - mn0), corr1 = __expf(mrow1 - mn1);
        mrow0 = mn0; mrow1 = mn1;

        float rs0 = 0.f, rs1 = 0.f;
        #pragma unroll
        for (int nt = 0; nt < 8; nt++) {
            float p0 = __expf(sacc[nt][0] - mn0);
            float p1 = __expf(sacc[nt][1] - mn0);
            float p2 = __expf(sacc[nt][2] - mn1);
            float p3 = __expf(sacc[nt][3] - mn1);
            rs0 += p0 + p1;  rs1 += p2 + p3;
            int cb = nt * 8 + 2 * tig;
            *(float2*)&Ps[(rA    ) * PS_S + cb] = make_float2(tf32r(p0), tf32r(p1));
            *(float2*)&Ps[(rA + 8) * PS_S + cb] = make_float2(tf32r(p2), tf32r(p3));
        }
        rs0 += __shfl_xor_sync(0xffffffffu, rs0, 1);
        rs0 += __shfl_xor_sync(0xffffffffu, rs0, 2);
        rs1 += __shfl_xor_sync(0xffffffffu, rs1, 1);
        rs1 += __shfl_xor_sync(0xffffffffu, rs1, 2);
        lrow0 = lrow0 * corr0 + rs0;
        lrow1 = lrow1 * corr1 + rs1;
        #pragma unroll
        for (int nt = 0; nt < 8; nt++) {
            oacc[nt][0] *= corr0; oacc[nt][1] *= corr0;
            oacc[nt][2] *= corr1; oacc[nt][3] *= corr1;
        }
        __syncwarp();   // warp reads only its own Ps rows

        // ---- O += P * V : rows same 16, cols 0..63 ----
        #pragma unroll
        for (int j0 = 0; j0 < 64; j0 += 8) {
            uint32_t a0 = f2u(Ps[(rA    ) * PS_S + j0 + tig    ]);
            uint32_t a1 = f2u(Ps[(rA + 8) * PS_S + j0 + tig    ]);
            uint32_t a2 = f2u(Ps[(rA    ) * PS_S + j0 + tig + 4]);
            uint32_t a3 = f2u(Ps[(rA + 8) * PS_S + j0 + tig + 4]);
            #pragma unroll
            for (int nt = 0; nt < 8; nt++) {
                uint32_t b0 = f2u(Vs[(nt * 8 + gid) * VS_S + j0 + tig    ]);
                uint32_t b1 = f2u(Vs[(nt * 8 + gid) * VS_S + j0 + tig + 4]);
                mma_tf32(oacc[nt], a0, a1, a2, a3, b0, b1);
            }
        }
    }

    // epilogue: a[b][h*64+c][i0+i] = oacc / l
    float inv0 = 1.f / lrow0, inv1 = 1.f / lrow1;
    size_t obase = ((size_t)b * Cn + h * CH) * Tn + i0;
    #pragma unroll
    for (int nt = 0; nt < 8; nt++) {
        int c = nt * 8 + 2 * tig;
        a_out[obase + (size_t)(c    ) * Tn + rA    ] = oacc[nt][0] * inv0;
        a_out[obase + (size_t)(c + 1) * Tn + rA    ] = oacc[nt][1] * inv0;
        a_out[obase + (size_t)(c    ) * Tn + rA + 8] = oacc[nt][2] * inv1;
        a_out[obase + (size_t)(c + 1) * Tn + rA + 8] = oacc[nt][3] * inv1;
    }
}

// ---------------------------------------------------------------------------
extern "C" void kernel_launch(void* const* d_in, const int* in_sizes, int n_in,
                              void* d_out, int out_size)
{
    const float* x      = (const float*)d_in[0];
    const float* gamma  = (const float*)d_in[1];
    const float* beta   = (const float*)d_in[2];
    const float* w_qkv  = (const float*)d_in[3];
    const float* b_qkv  = (const float*)d_in[4];
    const float* w_proj = (const float*)d_in[5];
    const float* b_proj = (const float*)d_in[6];
    float* out = (float*)d_out;

    float *h_ptr, *qkv_ptr, *a_ptr;
    cudaGetSymbolAddress((void**)&h_ptr,   g_h);
    cudaGetSymbolAddress((void**)&qkv_ptr, g_qkv);
    cudaGetSymbolAddress((void**)&a_ptr,   g_a);

    cudaFuncSetAttribute(attn_kernel,
                         cudaFuncAttributeMaxDynamicSharedMemorySize,
                         ATTN_SMEM_BYTES);

    // 1. GroupNorm
    gn_kernel<<<Bn * NG, 256>>>(x, gamma, beta, h_ptr);

    // 2. QKV GEMM (tf32 tensor cores, pipelined)
    sgemm_tf32<<<dim3(Tn / 128, 1536 / 128, Bn), 256>>>(
        w_qkv, h_ptr, b_qkv, nullptr, qkv_ptr, 1536, Cn, Tn);

    // 3. Attention (tf32 tensor cores, 2 CTAs/SM)
    attn_kernel<<<Bn * NH * (Tn / 128), 256, ATTN_SMEM_BYTES>>>(qkv_ptr, a_ptr);

    // 4. Proj GEMM + bias + residual
    sgemm_tf32<<<dim3(Tn / 128, Cn / 128, Bn), 256>>>(
        w_proj, a_ptr, b_proj, x, out, Cn, Cn, Tn);
}

// round 6
// speedup vs baseline: 4.7030x; 1.5217x over previous
#include <cuda_runtime.h>
#include <cstdint>

// Problem constants
constexpr int Bn   = 8;
constexpr int Cn   = 512;
constexpr int Tn   = 1024;
constexpr int NG   = 32;
constexpr int CPG  = Cn / NG;
constexpr int NH   = 8;
constexpr int CH   = 64;
constexpr float EPSV = 1e-5f;

// Scratch (device globals: allocation-free rule)
__device__ float g_h  [Bn * Cn   * Tn];
__device__ float g_qkv[Bn * 1536 * Tn];
__device__ float g_a  [Bn * Cn   * Tn];

// ---------------------------------------------------------------------------
// bf16 helpers: pack two fp32 into one bf16x2 word (lo = lower-k element)
// ---------------------------------------------------------------------------
__device__ __forceinline__ uint32_t bfpack(float lo, float hi) {
    uint32_t r;
    asm("cvt.rn.bf16x2.f32 %0, %1, %2;" : "=r"(r) : "f"(hi), "f"(lo));
    return r;
}

// D += A(16x16 row) * B(16x8 col);  fp32 accum, bf16 inputs
__device__ __forceinline__ void mma_bf16(float* c,
    uint32_t a0, uint32_t a1, uint32_t a2, uint32_t a3,
    uint32_t b0, uint32_t b1)
{
    asm volatile(
        "mma.sync.aligned.m16n8k16.row.col.f32.bf16.bf16.f32 "
        "{%0,%1,%2,%3}, {%4,%5,%6,%7}, {%8,%9}, {%0,%1,%2,%3};\n"
        : "+f"(c[0]), "+f"(c[1]), "+f"(c[2]), "+f"(c[3])
        : "r"(a0), "r"(a1), "r"(a2), "r"(a3), "r"(b0), "r"(b1));
}

// ---------------------------------------------------------------------------
// GroupNorm (HBM-bound, ~15us)
// ---------------------------------------------------------------------------
__global__ __launch_bounds__(256) void gn_kernel(
    const float* __restrict__ x, const float* __restrict__ gamma,
    const float* __restrict__ beta, float* __restrict__ out)
{
    int bg = blockIdx.x;
    int b = bg >> 5, g = bg & 31;
    const int CNT = CPG * Tn;
    size_t base = ((size_t)b * Cn + g * CPG) * Tn;

    float s = 0.f, s2 = 0.f;
    for (int i = threadIdx.x; i < CNT; i += 256) {
        float v = x[base + i];
        s += v; s2 += v * v;
    }
    #pragma unroll
    for (int o = 16; o > 0; o >>= 1) {
        s  += __shfl_down_sync(0xffffffffu, s,  o);
        s2 += __shfl_down_sync(0xffffffffu, s2, o);
    }
    __shared__ float ws[8], ws2[8], sMean, sRinv;
    int wid = threadIdx.x >> 5, lane = threadIdx.x & 31;
    if (lane == 0) { ws[wid] = s; ws2[wid] = s2; }
    __syncthreads();
    if (threadIdx.x == 0) {
        float ts = 0.f, ts2 = 0.f;
        #pragma unroll
        for (int i = 0; i < 8; i++) { ts += ws[i]; ts2 += ws2[i]; }
        float mean = ts / CNT;
        float var  = ts2 / CNT - mean * mean;
        sMean = mean;
        sRinv = rsqrtf(var + EPSV);
    }
    __syncthreads();
    float mean = sMean, rinv = sRinv;
    for (int i = threadIdx.x; i < CNT; i += 256) {
        int c = g * CPG + (i >> 10);
        out[base + i] = (x[base + i] - mean) * rinv * gamma[c] + beta[c];
    }
}

// ---------------------------------------------------------------------------
// bf16 tensor-core SGEMM, double-buffered pipeline.
// out[b][m][n] = sum_k W[m][k] X[b][k][n] + bias (+res);  fp32 in/out.
// 128x128 block tile, 8 warps (4m x 2n), warp tile 32x64, k-step 32
// (two m16n8k16 halves). SMEM holds packed bf16x2 words:
//   Ws_w[m][k2]  stride 20  (20%32==4*?  gid*20+tig covers all banks)
//   Xs_w[k2][n]  stride 136 (8*tig+gid covers all banks)
// ---------------------------------------------------------------------------
constexpr int WS_W = 20;    // words per row (16 + 4 pad)
constexpr int XS_W = 136;   // words per row (128 + 8 pad)

__global__ __launch_bounds__(256, 2) void sgemm_bf16(
    const float* __restrict__ W, const float* __restrict__ X,
    const float* __restrict__ bias, const float* __restrict__ resid,
    float* __restrict__ out, int O, int C, int T)
{
    __shared__ uint32_t Ws[2][128 * WS_W];   // 2 x 10,240 B
    __shared__ uint32_t Xs[2][16 * XS_W];    // 2 x  8,704 B

    int b  = blockIdx.z;
    const float* Xb = X + (size_t)b * C * T;
    float* outb     = out + (size_t)b * O * T;
    const float* rb = resid ? resid + (size_t)b * O * T : nullptr;
    int m0 = blockIdx.y * 128, n0 = blockIdx.x * 128;

    int tid = threadIdx.x, warp = tid >> 5, lane = tid & 31;
    int gid = lane >> 2, tig = lane & 3;
    int wm = warp >> 1;
    int wn = warp & 1;

    // staging indices
    int wm_e = tid >> 2,  wk_e = (tid & 3) * 8;     // W: rows wm_e, wm_e+64; k off
    int xk2_e = tid >> 5, xn_e = (tid & 31) * 4;    // X: k2 rows xk2_e, xk2_e+8

    float acc[2][8][4];
    #pragma unroll
    for (int mt = 0; mt < 2; mt++)
        #pragma unroll
        for (int nt = 0; nt < 8; nt++)
            #pragma unroll
            for (int q = 0; q < 4; q++) acc[mt][nt][q] = 0.f;

    // prologue: prefetch tile 0
    float4 w00 = *(const float4*)&W[(size_t)(m0 + wm_e     ) * C + wk_e];
    float4 w01 = *(const float4*)&W[(size_t)(m0 + wm_e     ) * C + wk_e + 4];
    float4 w10 = *(const float4*)&W[(size_t)(m0 + wm_e + 64) * C + wk_e];
    float4 w11 = *(const float4*)&W[(size_t)(m0 + wm_e + 64) * C + wk_e + 4];
    float4 x00 = *(const float4*)&Xb[(size_t)(2 * xk2_e     ) * T + n0 + xn_e];
    float4 x01 = *(const float4*)&Xb[(size_t)(2 * xk2_e  + 1) * T + n0 + xn_e];
    float4 x10 = *(const float4*)&Xb[(size_t)(2 * xk2_e + 16) * T + n0 + xn_e];
    float4 x11 = *(const float4*)&Xb[(size_t)(2 * xk2_e + 17) * T + n0 + xn_e];

    int nk = C >> 5;   // k-tiles of 32
    for (int i = 0; i < nk; i++) {
        int p = i & 1;
        // commit prefetched tile to smem as packed bf16x2
        *(uint4*)&Ws[p][wm_e * WS_W + (wk_e >> 1)] =
            make_uint4(bfpack(w00.x, w00.y), bfpack(w00.z, w00.w),
                       bfpack(w01.x, w01.y), bfpack(w01.z, w01.w));
        *(uint4*)&Ws[p][(wm_e + 64) * WS_W + (wk_e >> 1)] =
            make_uint4(bfpack(w10.x, w10.y), bfpack(w10.z, w10.w),
                       bfpack(w11.x, w11.y), bfpack(w11.z, w11.w));
        *(uint4*)&Xs[p][xk2_e * XS_W + xn_e] =
            make_uint4(bfpack(x00.x, x01.x), bfpack(x00.y, x01.y),
                       bfpack(x00.z, x01.z), bfpack(x00.w, x01.w));
        *(uint4*)&Xs[p][(xk2_e + 8) * XS_W + xn_e] =
            make_uint4(bfpack(x10.x, x11.x), bfpack(x10.y, x11.y),
                       bfpack(x10.z, x11.z), bfpack(x10.w, x11.w));
        __syncthreads();

        // issue next tile's gmem loads (land during compute)
        if (i + 1 < nk) {
            int k0 = (i + 1) << 5;
            w00 = *(const float4*)&W[(size_t)(m0 + wm_e     ) * C + k0 + wk_e];
            w01 = *(const float4*)&W[(size_t)(m0 + wm_e     ) * C + k0 + wk_e + 4];
            w10 = *(const float4*)&W[(size_t)(m0 + wm_e + 64) * C + k0 + wk_e];
            w11 = *(const float4*)&W[(size_t)(m0 + wm_e + 64) * C + k0 + wk_e + 4];
            x00 = *(const float4*)&Xb[(size_t)(k0 + 2 * xk2_e     ) * T + n0 + xn_e];
            x01 = *(const float4*)&Xb[(size_t)(k0 + 2 * xk2_e  + 1) * T + n0 + xn_e];
            x10 = *(const float4*)&Xb[(size_t)(k0 + 2 * xk2_e + 16) * T + n0 + xn_e];
            x11 = *(const float4*)&Xb[(size_t)(k0 + 2 * xk2_e + 17) * T + n0 + xn_e];
        }

        #pragma unroll
        for (int kh = 0; kh < 2; kh++) {
            int kho = kh * 8;
            uint32_t a[2][4];
            #pragma unroll
            for (int mt = 0; mt < 2; mt++) {
                int rbse = wm * 32 + mt * 16;
                a[mt][0] = Ws[p][(rbse + gid    ) * WS_W + kho + tig    ];
                a[mt][1] = Ws[p][(rbse + gid + 8) * WS_W + kho + tig    ];
                a[mt][2] = Ws[p][(rbse + gid    ) * WS_W + kho + tig + 4];
                a[mt][3] = Ws[p][(rbse + gid + 8) * WS_W + kho + tig + 4];
            }
            #pragma unroll
            for (int nt = 0; nt < 8; nt++) {
                int cb = wn * 64 + nt * 8;
                uint32_t b0 = Xs[p][(kho + tig    ) * XS_W + cb + gid];
                uint32_t b1 = Xs[p][(kho + tig + 4) * XS_W + cb + gid];
                #pragma unroll
                for (int mt = 0; mt < 2; mt++)
                    mma_bf16(acc[mt][nt], a[mt][0], a[mt][1], a[mt][2], a[mt][3], b0, b1);
            }
        }
    }

    // epilogue (fp32)
    #pragma unroll
    for (int mt = 0; mt < 2; mt++) {
        #pragma unroll
        for (int rr = 0; rr < 2; rr++) {
            int m = m0 + wm * 32 + mt * 16 + gid + rr * 8;
            float bi = bias[m];
            #pragma unroll
            for (int nt = 0; nt < 8; nt++) {
                int n = n0 + wn * 64 + nt * 8 + 2 * tig;
                float v0 = acc[mt][nt][rr * 2 + 0] + bi;
                float v1 = acc[mt][nt][rr * 2 + 1] + bi;
                if (rb) {
                    v0 += rb[(size_t)m * T + n];
                    v1 += rb[(size_t)m * T + n + 1];
                }
                *(float2*)&outb[(size_t)m * T + n] = make_float2(v0, v1);
            }
        }
    }
}

// ---------------------------------------------------------------------------
// Flash attention, bf16 m16n8k16, 128-wide S tiles (8 iters), 2 CTAs/SM.
// Warp owns 16 full S rows -> softmax needs only quad shuffles.
// Packed-word SMEM (all fragment loads conflict-free):
//   Qs[i][c2]  stride 36   (a-frag: 4*gid+tig)
//   Ks[c2][j]  stride 136  (b-frag: 8*tig+gid)
//   Vs[c][j2]  stride 68   (b-frag: 4*gid+tig)
//   Ps[i][j2]  stride 68   (a-frag: 4*gid+tig; stores conflict-free too)
// ---------------------------------------------------------------------------
constexpr int QS_W = 36;
constexpr int KS_W = 136;
constexpr int VS_W = 68;
constexpr int PS_W = 68;

constexpr int ATTN_SMEM_WORDS = 128 * QS_W + 32 * KS_W + 64 * VS_W + 128 * PS_W;
constexpr int ATTN_SMEM_BYTES = ATTN_SMEM_WORDS * 4;  // 88,064 B -> 2 CTAs/SM

__global__ __launch_bounds__(256, 2) void attn_kernel(
    const float* __restrict__ qkv, float* __restrict__ a_out)
{
    extern __shared__ uint32_t sm[];
    uint32_t* Qs = sm;                       // [i][c2]
    uint32_t* Ks = Qs + 128 * QS_W;          // [c2][j]
    uint32_t* Vs = Ks + 32 * KS_W;           // [c][j2]
    uint32_t* Ps = Vs + 64 * VS_W;           // [i][j2]

    int blk = blockIdx.x;
    int qt = blk & 7, hh = blk >> 3;
    int b = hh >> 3, h = hh & 7;
    const float* qb = qkv + ((size_t)b * 1536 + h * 192) * Tn;
    const float* kb = qb + 64 * Tn;
    const float* vb = qb + 128 * Tn;
    int i0 = qt * 128;

    int tid = threadIdx.x, warp = tid >> 5, lane = tid & 31;
    int gid = lane >> 2, tig = lane & 3;
    int rA = warp * 16 + gid;        // first row; second is rA + 8

    // load Q packed: Qs[i][c2] = bf16x2(q[2c2][i], q[2c2+1][i]) * 0.125
    #pragma unroll 4
    for (int e = tid; e < 32 * 128; e += 256) {
        int i = e & 127, c2 = e >> 7;
        float lo = qb[(size_t)(2 * c2    ) * Tn + i0 + i] * 0.125f;
        float hi = qb[(size_t)(2 * c2 + 1) * Tn + i0 + i] * 0.125f;
        Qs[i * QS_W + c2] = bfpack(lo, hi);
    }

    float mrow0 = -1e30f, mrow1 = -1e30f;
    float lrow0 = 0.f, lrow1 = 0.f;
    float oacc[8][4];
    #pragma unroll
    for (int nt = 0; nt < 8; nt++)
        #pragma unroll
        for (int q = 0; q < 4; q++) oacc[nt][q] = 0.f;

    for (int s0 = 0; s0 < Tn; s0 += 128) {
        __syncthreads();   // prior tile's S/PV done with Ks/Vs; Qs ready
        // stage K packed across c-pairs: Ks[c2][j]
        #pragma unroll 4
        for (int e = tid; e < 32 * 128; e += 256) {
            int j = e & 127, c2 = e >> 7;
            Ks[c2 * KS_W + j] = bfpack(kb[(size_t)(2 * c2    ) * Tn + s0 + j],
                                       kb[(size_t)(2 * c2 + 1) * Tn + s0 + j]);
        }
        // stage V packed across j-pairs: Vs[c][j2]
        #pragma unroll 2
        for (int e = tid; e < 64 * 32; e += 256) {
            int j4 = e & 31, c = e >> 5;
            float4 v = *(const float4*)&vb[(size_t)c * Tn + s0 + 4 * j4];
            Vs[c * VS_W + 2 * j4    ] = bfpack(v.x, v.y);
            Vs[c * VS_W + 2 * j4 + 1] = bfpack(v.z, v.w);
        }
        __syncthreads();

        // ---- S = Q^T K : rows [warp*16,+16), cols 0..127 ----
        float sacc[16][4];
        #pragma unroll
        for (int nt = 0; nt < 16; nt++)
            #pragma unroll
            for (int q = 0; q < 4; q++) sacc[nt][q] = 0.f;

        #pragma unroll
        for (int c2o = 0; c2o < 32; c2o += 8) {
            uint32_t a0 = Qs[(rA    ) * QS_W + c2o + tig    ];
            uint32_t a1 = Qs[(rA + 8) * QS_W + c2o + tig    ];
            uint32_t a2 = Qs[(rA    ) * QS_W + c2o + tig + 4];
            uint32_t a3 = Qs[(rA + 8) * QS_W + c2o + tig + 4];
            #pragma unroll
            for (int nt = 0; nt < 16; nt++) {
                uint32_t b0 = Ks[(c2o + tig    ) * KS_W + nt * 8 + gid];
                uint32_t b1 = Ks[(c2o + tig + 4) * KS_W + nt * 8 + gid];
                mma_bf16(sacc[nt], a0, a1, a2, a3, b0, b1);
            }
        }

        // ---- online softmax (rows rA and rA+8; reduce across quad) ----
        float mx0 = -1e30f, mx1 = -1e30f;
        #pragma unroll
        for (int nt = 0; nt < 16; nt++) {
            mx0 = fmaxf(mx0, fmaxf(sacc[nt][0], sacc[nt][1]));
            mx1 = fmaxf(mx1, fmaxf(sacc[nt][2], sacc[nt][3]));
        }
        mx0 = fmaxf(mx0, __shfl_xor_sync(0xffffffffu, mx0, 1));
        mx0 = fmaxf(mx0, __shfl_xor_sync(0xffffffffu, mx0, 2));
        mx1 = fmaxf(mx1, __shfl_xor_sync(0xffffffffu, mx1, 1));
        mx1 = fmaxf(mx1, __shfl_xor_sync(0xffffffffu, mx1, 2));
        float mn0 = fmaxf(mrow0, mx0), mn1 = fmaxf(mrow1, mx1);
        float corr0 = __expf(mrow0 - mn0), corr1 = __expf(mrow1 - mn1);
        mrow0 = mn0; mrow1 = mn1;

        float rs0 = 0.f, rs1 = 0.f;
        #pragma unroll
        for (int nt = 0; nt < 16; nt++) {
            float p0 = __expf(sacc[nt][0] - mn0);
            float p1 = __expf(sacc[nt][1] - mn0);
            float p2 = __expf(sacc[nt][2] - mn1);
            float p3 = __expf(sacc[nt][3] - mn1);
            rs0 += p0 + p1;  rs1 += p2 + p3;
            Ps[(rA    ) * PS_W + nt * 4 + tig] = bfpack(p0, p1);
            Ps[(rA + 8) * PS_W + nt * 4 + tig] = bfpack(p2, p3);
        }
        rs0 += __shfl_xor_sync(0xffffffffu, rs0, 1);
        rs0 += __shfl_xor_sync(0xffffffffu, rs0, 2);
        rs1 += __shfl_xor_sync(0xffffffffu, rs1, 1);
        rs1 += __shfl_xor_sync(0xffffffffu, rs1, 2);
        lrow0 = lrow0 * corr0 + rs0;
        lrow1 = lrow1 * corr1 + rs1;
        #pragma unroll
        for (int nt = 0; nt < 8; nt++) {
            oacc[nt][0] *= corr0; oacc[nt][1] *= corr0;
            oacc[nt][2] *= corr1; oacc[nt][3] *= corr1;
        }
        __syncwarp();   // warp reads only its own Ps rows

        // ---- O += P * V : rows same 16, cols 0..63 ----
        #pragma unroll
        for (int j2o = 0; j2o < 64; j2o += 8) {
            uint32_t a0 = Ps[(rA    ) * PS_W + j2o + tig    ];
            uint32_t a1 = Ps[(rA + 8) * PS_W + j2o + tig    ];
            uint32_t a2 = Ps[(rA    ) * PS_W + j2o + tig + 4];
            uint32_t a3 = Ps[(rA + 8) * PS_W + j2o + tig + 4];
            #pragma unroll
            for (int nt = 0; nt < 8; nt++) {
                uint32_t b0 = Vs[(nt * 8 + gid) * VS_W + j2o + tig    ];
                uint32_t b1 = Vs[(nt * 8 + gid) * VS_W + j2o + tig + 4];
                mma_bf16(oacc[nt], a0, a1, a2, a3, b0, b1);
            }
        }
    }

    // epilogue: a[b][h*64+c][i0+i] = oacc / l
    float inv0 = 1.f / lrow0, inv1 = 1.f / lrow1;
    size_t obase = ((size_t)b * Cn + h * CH) * Tn + i0;
    #pragma unroll
    for (int nt = 0; nt < 8; nt++) {
        int c = nt * 8 + 2 * tig;
        a_out[obase + (size_t)(c    ) * Tn + rA    ] = oacc[nt][0] * inv0;
        a_out[obase + (size_t)(c + 1) * Tn + rA    ] = oacc[nt][1] * inv0;
        a_out[obase + (size_t)(c    ) * Tn + rA + 8] = oacc[nt][2] * inv1;
        a_out[obase + (size_t)(c + 1) * Tn + rA + 8] = oacc[nt][3] * inv1;
    }
}

// ---------------------------------------------------------------------------
extern "C" void kernel_launch(void* const* d_in, const int* in_sizes, int n_in,
                              void* d_out, int out_size)
{
    const float* x      = (const float*)d_in[0];
    const float* gamma  = (const float*)d_in[1];
    const float* beta   = (const float*)d_in[2];
    const float* w_qkv  = (const float*)d_in[3];
    const float* b_qkv  = (const float*)d_in[4];
    const float* w_proj = (const float*)d_in[5];
    const float* b_proj = (const float*)d_in[6];
    float* out = (float*)d_out;

    float *h_ptr, *qkv_ptr, *a_ptr;
    cudaGetSymbolAddress((void**)&h_ptr,   g_h);
    cudaGetSymbolAddress((void**)&qkv_ptr, g_qkv);
    cudaGetSymbolAddress((void**)&a_ptr,   g_a);

    cudaFuncSetAttribute(attn_kernel,
                         cudaFuncAttributeMaxDynamicSharedMemorySize,
                         ATTN_SMEM_BYTES);

    // 1. GroupNorm
    gn_kernel<<<Bn * NG, 256>>>(x, gamma, beta, h_ptr);

    // 2. QKV GEMM (bf16 tensor cores, pipelined)
    sgemm_bf16<<<dim3(Tn / 128, 1536 / 128, Bn), 256>>>(
        w_qkv, h_ptr, b_qkv, nullptr, qkv_ptr, 1536, Cn, Tn);

    // 3. Attention (bf16 tensor cores, 2 CTAs/SM)
    attn_kernel<<<Bn * NH * (Tn / 128), 256, ATTN_SMEM_BYTES>>>(qkv_ptr, a_ptr);

    // 4. Proj GEMM + bias + residual
    sgemm_bf16<<<dim3(Tn / 128, Cn / 128, Bn), 256>>>(
        w_proj, a_ptr, b_proj, x, out, Cn, Cn, Tn);
}